// round 1
// baseline (speedup 1.0000x reference)
#include <cuda_runtime.h>
#include <cstdint>
#include <math.h>

#define Bdim 128
#define Tdim 32
#define Edim 512
#define Hdim 1024
#define G4   4096
#define Vdim 32000

// ---------------- device scratch (no allocations allowed) ----------------
__device__ __align__(16) float g_X[Bdim * Tdim * Edim];        // 8 MB
__device__ __align__(16) float g_G0[Bdim * Tdim * G4];         // 64 MB
__device__ __align__(16) float g_h0[2][Tdim * Hdim];
__device__ __align__(16) float g_h1[2][Tdim * Hdim];
__device__ __align__(16) float g_c0[Tdim * Hdim];
__device__ __align__(16) float g_c1[Tdim * Hdim];
__device__ __align__(16) float g_ys[Bdim * Tdim * Hdim];       // 16 MB
__device__ __align__(16) float g_bias1[G4];

// ---------------- helpers ----------------
__device__ __forceinline__ uint32_t f2tf(float x) {
    uint32_t r;
    asm("cvt.rna.tf32.f32 %0, %1;" : "=r"(r) : "f"(x));
    return r;
}

__device__ __forceinline__ void mma_tf32(float c[4], const uint32_t a[4], const uint32_t b[2]) {
    asm volatile(
        "mma.sync.aligned.m16n8k8.row.col.f32.tf32.tf32.f32 "
        "{%0,%1,%2,%3}, {%4,%5,%6,%7}, {%8,%9}, {%0,%1,%2,%3};"
        : "+f"(c[0]), "+f"(c[1]), "+f"(c[2]), "+f"(c[3])
        : "r"(a[0]), "r"(a[1]), "r"(a[2]), "r"(a[3]), "r"(b[0]), "r"(b[1]));
}

__device__ __forceinline__ void cp16(float* s, const float* g) {
    uint32_t sa = (uint32_t)__cvta_generic_to_shared(s);
    asm volatile("cp.async.cg.shared.global [%0], [%1], 16;" :: "r"(sa), "l"(g));
}
__device__ __forceinline__ void cp_commit() { asm volatile("cp.async.commit_group;"); }

__device__ __forceinline__ float sigm(float x) { return 1.f / (1.f + expf(-x)); }

// ---------------- init: zero states, combined layer-1 bias ----------------
__global__ void init_kernel(const float* __restrict__ b_ih1, const float* __restrict__ b_hh1) {
    int i = blockIdx.x * blockDim.x + threadIdx.x;
    if (i < Tdim * Hdim) {
        g_h0[0][i] = 0.f; g_h1[0][i] = 0.f;
        g_c0[i] = 0.f;    g_c1[i] = 0.f;
    }
    if (i < G4) g_bias1[i] = b_ih1[i] + b_hh1[i];
}

// ---------------- build X: t==0 -> features, t>=1 -> embed ----------------
__global__ void build_x(const float* __restrict__ features, const int* __restrict__ captions,
                        const float* __restrict__ embW) {
    int b = blockIdx.x, t = blockIdx.y;
    const float* src = (t == 0) ? (features + (size_t)b * Edim)
                                : (embW + (size_t)captions[b * Tdim + t] * Edim);
    float4* dst = reinterpret_cast<float4*>(g_X + ((size_t)b * Tdim + t) * Edim);
    const float4* s4 = reinterpret_cast<const float4*>(src);
    dst[threadIdx.x] = s4[threadIdx.x];   // 128 threads * float4 = 512 floats
}

// ---------------- big tf32 GEMM: C[M,N] = A[M,K] @ W[N,K]^T + bias ----------------
#define BM 128
#define BN 256
#define BKx 32
#define LDSS 36   // padded row stride (floats): bank = (4m+k)%32 all distinct

__global__ void __launch_bounds__(256, 1) gemm_tf32(
    const float* __restrict__ A, const float* __restrict__ W,
    const float* __restrict__ bias0, const float* __restrict__ bias1,
    float* __restrict__ C, int M, int N, int K)
{
    extern __shared__ float smem_f[];
    float* As = smem_f;                    // [2][BM][LDSS]
    float* Bs = smem_f + 2 * BM * LDSS;    // [2][BN][LDSS]

    int tid = threadIdx.x;
    int lane = tid & 31, warp = tid >> 5;
    int m0 = blockIdx.x * BM, n0 = blockIdx.y * BN;
    int wm = (warp >> 2) * 64, wn = (warp & 3) * 64;

    float acc[4][8][4];
    #pragma unroll
    for (int a = 0; a < 4; a++)
        #pragma unroll
        for (int b = 0; b < 8; b++)
            #pragma unroll
            for (int c = 0; c < 4; c++) acc[a][b][c] = 0.f;

    auto load_stage = [&](int s, int buf) {
        int k0 = s * BKx;
        const float* Ag = A + (size_t)m0 * K + k0;
        #pragma unroll
        for (int i = 0; i < 4; i++) {
            int idx = tid + i * 256;
            int m = idx >> 3, seg = idx & 7;
            cp16(&As[buf * BM * LDSS + m * LDSS + seg * 4], Ag + (size_t)m * K + seg * 4);
        }
        const float* Wg = W + (size_t)n0 * K + k0;
        #pragma unroll
        for (int i = 0; i < 8; i++) {
            int idx = tid + i * 256;
            int n = idx >> 3, seg = idx & 7;
            cp16(&Bs[buf * BN * LDSS + n * LDSS + seg * 4], Wg + (size_t)n * K + seg * 4);
        }
        cp_commit();
    };

    int S = K / BKx;
    load_stage(0, 0);
    for (int s = 0; s < S; s++) {
        int buf = s & 1;
        if (s + 1 < S) {
            load_stage(s + 1, buf ^ 1);
            asm volatile("cp.async.wait_group 1;");
        } else {
            asm volatile("cp.async.wait_group 0;");
        }
        __syncthreads();
        const float* Ab = &As[buf * BM * LDSS];
        const float* Bb = &Bs[buf * BN * LDSS];
        #pragma unroll
        for (int kc = 0; kc < 4; kc++) {
            uint32_t af[4][4];
            #pragma unroll
            for (int mt = 0; mt < 4; mt++) {
                int r = wm + mt * 16 + (lane >> 2);
                const float* p = Ab + r * LDSS + kc * 8 + (lane & 3);
                af[mt][0] = f2tf(p[0]);
                af[mt][1] = f2tf(p[8 * LDSS]);
                af[mt][2] = f2tf(p[4]);
                af[mt][3] = f2tf(p[8 * LDSS + 4]);
            }
            #pragma unroll
            for (int nt = 0; nt < 8; nt++) {
                int n = wn + nt * 8 + (lane >> 2);
                const float* p = Bb + n * LDSS + kc * 8 + (lane & 3);
                uint32_t bf[2] = { f2tf(p[0]), f2tf(p[4]) };
                #pragma unroll
                for (int mt = 0; mt < 4; mt++) mma_tf32(acc[mt][nt], af[mt], bf);
            }
        }
        __syncthreads();
    }

    #pragma unroll
    for (int nt = 0; nt < 8; nt++) {
        int col = n0 + wn + nt * 8 + 2 * (lane & 3);
        float bv0 = bias0[col], bv1 = bias0[col + 1];
        if (bias1) { bv0 += bias1[col]; bv1 += bias1[col + 1]; }
        #pragma unroll
        for (int mt = 0; mt < 4; mt++) {
            int row = m0 + wm + mt * 16 + (lane >> 2);
            float2 v;
            v.x = acc[mt][nt][0] + bv0; v.y = acc[mt][nt][1] + bv1;
            *reinterpret_cast<float2*>(C + (size_t)row * N + col) = v;
            v.x = acc[mt][nt][2] + bv0; v.y = acc[mt][nt][3] + bv1;
            *reinterpret_cast<float2*>(C + (size_t)(row + 8) * N + col) = v;
        }
    }
}

// ---------------- per-step fused LSTM layer kernel ----------------
// gates[32, 4H] = base + A0 @ W0^T (+ A1 @ W1^T), then pointwise c/h update.
// Grid: 128 blocks, each owns 8 hidden columns (all 4 gate strips).
// 8 warps split K; SMEM reduction; fused sigmoid/tanh epilogue.
template <int LAYER>
__global__ void __launch_bounds__(256, 1) lstm_step(
    const float* __restrict__ W0, const float* __restrict__ W1, int b, int par)
{
    const float* A0 = (LAYER == 0) ? g_h0[par] : g_h0[par ^ 1];
    const float* A1 = (LAYER == 0) ? nullptr : g_h1[par];
    float* cbuf = (LAYER == 0) ? g_c0 : g_c1;
    float* hout = (LAYER == 0) ? g_h0[par ^ 1] : g_h1[par ^ 1];

    __shared__ float red[8 * 4 * 2 * 16 * 8];  // [warp][gate][mt][row16][col8]
    __shared__ float gs[4][32][8];

    int tid = threadIdx.x, lane = tid & 31, warp = tid >> 5;
    int j0 = blockIdx.x * 8;

    float acc[4][2][4];
    #pragma unroll
    for (int g = 0; g < 4; g++)
        #pragma unroll
        for (int mt = 0; mt < 2; mt++)
            #pragma unroll
            for (int c = 0; c < 4; c++) acc[g][mt][c] = 0.f;

    int kbase = warp * 128;

    // GEMM 1: A0 @ W0^T
    #pragma unroll 4
    for (int kc = 0; kc < 16; kc++) {
        int k0 = kbase + kc * 8 + (lane & 3);
        uint32_t af[2][4];
        #pragma unroll
        for (int mt = 0; mt < 2; mt++) {
            int r = mt * 16 + (lane >> 2);
            af[mt][0] = f2tf(A0[r * Hdim + k0]);
            af[mt][1] = f2tf(A0[(r + 8) * Hdim + k0]);
            af[mt][2] = f2tf(A0[r * Hdim + k0 + 4]);
            af[mt][3] = f2tf(A0[(r + 8) * Hdim + k0 + 4]);
        }
        #pragma unroll
        for (int g = 0; g < 4; g++) {
            int n = g * 1024 + j0 + (lane >> 2);
            uint32_t bf[2] = { f2tf(W0[(size_t)n * Hdim + k0]),
                               f2tf(W0[(size_t)n * Hdim + k0 + 4]) };
            mma_tf32(acc[g][0], af[0], bf);
            mma_tf32(acc[g][1], af[1], bf);
        }
    }

    // GEMM 2 (layer 1 only): A1 @ W1^T
    if (LAYER == 1) {
        #pragma unroll 4
        for (int kc = 0; kc < 16; kc++) {
            int k0 = kbase + kc * 8 + (lane & 3);
            uint32_t af[2][4];
            #pragma unroll
            for (int mt = 0; mt < 2; mt++) {
                int r = mt * 16 + (lane >> 2);
                af[mt][0] = f2tf(A1[r * Hdim + k0]);
                af[mt][1] = f2tf(A1[(r + 8) * Hdim + k0]);
                af[mt][2] = f2tf(A1[r * Hdim + k0 + 4]);
                af[mt][3] = f2tf(A1[(r + 8) * Hdim + k0 + 4]);
            }
            #pragma unroll
            for (int g = 0; g < 4; g++) {
                int n = g * 1024 + j0 + (lane >> 2);
                uint32_t bf[2] = { f2tf(W1[(size_t)n * Hdim + k0]),
                                   f2tf(W1[(size_t)n * Hdim + k0 + 4]) };
                mma_tf32(acc[g][0], af[0], bf);
                mma_tf32(acc[g][1], af[1], bf);
            }
        }
    }

    // stash warp partials
    #pragma unroll
    for (int g = 0; g < 4; g++)
        #pragma unroll
        for (int mt = 0; mt < 2; mt++) {
            float* base = red + (((warp * 4 + g) * 2 + mt) * 16) * 8;
            int r = lane >> 2, c = 2 * (lane & 3);
            *reinterpret_cast<float2*>(base + r * 8 + c) = make_float2(acc[g][mt][0], acc[g][mt][1]);
            *reinterpret_cast<float2*>(base + (r + 8) * 8 + c) = make_float2(acc[g][mt][2], acc[g][mt][3]);
        }
    __syncthreads();

    // cross-warp reduction + base term
    #pragma unroll
    for (int i = 0; i < 4; i++) {
        int idx = tid + i * 256;
        int g = idx >> 8, rem = idx & 255;
        int t = rem >> 3, j = rem & 7;
        int mt = t >> 4, row = t & 15;
        float s = 0.f;
        #pragma unroll
        for (int w = 0; w < 8; w++) s += red[(((w * 4 + g) * 2 + mt) * 16 + row) * 8 + j];
        if (LAYER == 0) s += g_G0[((size_t)(b * 32 + t)) * G4 + g * 1024 + j0 + j];
        else            s += g_bias1[g * 1024 + j0 + j];
        gs[g][t][j] = s;
    }
    __syncthreads();

    // pointwise LSTM cell update (one thread per (t, j))
    {
        int t = tid >> 3, j = tid & 7, jg = j0 + j;
        float iv = gs[0][t][j], fv = gs[1][t][j], gv = gs[2][t][j], ov = gs[3][t][j];
        float cn = sigm(fv) * cbuf[t * Hdim + jg] + sigm(iv) * tanhf(gv);
        float hn = sigm(ov) * tanhf(cn);
        cbuf[t * Hdim + jg] = cn;
        hout[t * Hdim + jg] = hn;
        if (LAYER == 1) g_ys[((size_t)(b * 32 + t)) * Hdim + jg] = hn;
    }
}

// ---------------- launch ----------------
extern "C" void kernel_launch(void* const* d_in, const int* in_sizes, int n_in,
                              void* d_out, int out_size)
{
    const float* features = (const float*)d_in[0];
    const int*   captions = (const int*)d_in[1];
    const float* embed_W  = (const float*)d_in[2];
    const float* W_ih0    = (const float*)d_in[3];
    const float* W_hh0    = (const float*)d_in[4];
    const float* b_ih0    = (const float*)d_in[5];
    const float* b_hh0    = (const float*)d_in[6];
    const float* W_ih1    = (const float*)d_in[7];
    const float* W_hh1    = (const float*)d_in[8];
    const float* b_ih1    = (const float*)d_in[9];
    const float* b_hh1    = (const float*)d_in[10];
    const float* fc_W     = (const float*)d_in[11];
    const float* fc_b     = (const float*)d_in[12];
    float* out = (float*)d_out;

    void *pX = nullptr, *pG0 = nullptr, *pys = nullptr;
    cudaGetSymbolAddress(&pX, g_X);
    cudaGetSymbolAddress(&pG0, g_G0);
    cudaGetSymbolAddress(&pys, g_ys);

    size_t smem = (size_t)(2 * (BM + BN) * LDSS) * sizeof(float);  // 108 KB
    cudaFuncSetAttribute(gemm_tf32, cudaFuncAttributeMaxDynamicSharedMemorySize, (int)smem);

    init_kernel<<<((Tdim * Hdim) + 255) / 256, 256>>>(b_ih1, b_hh1);
    build_x<<<dim3(Bdim, Tdim), 128>>>(features, captions, embed_W);

    // G0 = X @ W_ih0^T + b_ih0 + b_hh0   (M=4096, N=4096, K=512)
    gemm_tf32<<<dim3(G4 / BM, G4 / BN), 256, smem>>>(
        (const float*)pX, W_ih0, b_ih0, b_hh0, (float*)pG0, Bdim * Tdim, G4, Edim);

    for (int b = 0; b < Bdim; b++) {
        int par = b & 1;
        lstm_step<0><<<128, 256>>>(W_hh0, nullptr, b, par);
        lstm_step<1><<<128, 256>>>(W_ih1, W_hh1, b, par);
    }

    // logits = ys @ fc_W^T + fc_b   (M=4096, N=32000, K=1024)
    gemm_tf32<<<dim3((Bdim * Tdim) / BM, Vdim / BN), 256, smem>>>(
        (const float*)pys, fc_W, fc_b, nullptr, out, Bdim * Tdim, Vdim, Hdim);
}